// round 4
// baseline (speedup 1.0000x reference)
#include <cuda_runtime.h>
#include <cuda_bf16.h>
#include <cstdint>

// Problem constants (fixed by reference setup_inputs)
#define BB   8
#define SS   2048
#define KK   16
#define RR   16
#define DIN  2048
#define DOUT 2048

// Scratch (device globals: allocation-rule safe)
__device__ float g_Amix[BB * RR * DIN];          // [b][r][i]   1 MB
__device__ float g_BT[BB * RR * DOUT];           // [b][r][o]   1 MB (B_mixed transposed)
__device__ float g_zpart[4][BB * SS * RR];       // [split][b][s][r]  4 MB

// ---------------- f32x2 packed-FMA helpers (sm_100+ PTX) ----------------
__device__ __forceinline__ unsigned long long pack2(float x, float y) {
    unsigned long long r;
    asm("mov.b64 %0, {%1,%2};" : "=l"(r) : "f"(x), "f"(y));
    return r;
}
__device__ __forceinline__ float2 unpack2(unsigned long long v) {
    float2 f;
    asm("mov.b64 {%0,%1}, %2;" : "=f"(f.x), "=f"(f.y) : "l"(v));
    return f;
}
__device__ __forceinline__ void fma2(unsigned long long& c,
                                     unsigned long long a,
                                     unsigned long long b) {
    asm("fma.rn.f32x2 %0, %1, %2, %3;" : "=l"(c) : "l"(a), "l"(b), "l"(c));
}

// ---------------- mixA: A_mixed[b][r][i] = sum_k alpha[b,k] * A_bank[k,r,i] ----------------
__global__ void __launch_bounds__(256) mixA_kernel(const float* __restrict__ alpha,
                                                   const float* __restrict__ Abank) {
    int r = blockIdx.x;   // 0..15
    int b = blockIdx.y;   // 0..7
    __shared__ float al[KK];
    if (threadIdx.x < KK) al[threadIdx.x] = alpha[b * KK + threadIdx.x];
    __syncthreads();

    for (int i = threadIdx.x * 4; i < DIN; i += 256 * 4) {
        float4 acc = make_float4(0.f, 0.f, 0.f, 0.f);
#pragma unroll
        for (int k = 0; k < KK; k++) {
            float a = al[k];
            float4 v = *(const float4*)&Abank[((size_t)(k * RR + r)) * DIN + i];
            acc.x = fmaf(a, v.x, acc.x);
            acc.y = fmaf(a, v.y, acc.y);
            acc.z = fmaf(a, v.z, acc.z);
            acc.w = fmaf(a, v.w, acc.w);
        }
        *(float4*)&g_Amix[((size_t)(b * RR + r)) * DIN + i] = acc;
    }
}

// ---------------- mixB: g_BT[b][r][o] = sum_k alpha[b,k] * B_bank[k][o][r] ----------------
__global__ void __launch_bounds__(256) mixB_kernel(const float* __restrict__ alpha,
                                                   const float* __restrict__ Bbank) {
    int b = blockIdx.y;
    int o = blockIdx.x * 256 + threadIdx.x;
    __shared__ float al[KK];
    if (threadIdx.x < KK) al[threadIdx.x] = alpha[b * KK + threadIdx.x];
    __syncthreads();

    float acc[RR];
#pragma unroll
    for (int r = 0; r < RR; r++) acc[r] = 0.f;

#pragma unroll
    for (int k = 0; k < KK; k++) {
        float a = al[k];
        const float4* p = (const float4*)&Bbank[(((size_t)k * DOUT) + o) * RR];
#pragma unroll
        for (int q = 0; q < 4; q++) {
            float4 v = p[q];
            acc[4 * q + 0] = fmaf(a, v.x, acc[4 * q + 0]);
            acc[4 * q + 1] = fmaf(a, v.y, acc[4 * q + 1]);
            acc[4 * q + 2] = fmaf(a, v.z, acc[4 * q + 2]);
            acc[4 * q + 3] = fmaf(a, v.w, acc[4 * q + 3]);
        }
    }
#pragma unroll
    for (int r = 0; r < RR; r++)
        g_BT[((size_t)(b * RR + r)) * DOUT + o] = acc[r];
}

// ---------------- zkern: z[b,s,r] = sum_i A_mixed[b,r,i] * h[b,s,i] (k-split of 4) -------
// grid: (sTiles=8, ksplit=4, b=8), block = 128
#define TS1 256   // s rows per block
#define TK1 32    // k chunk
#define P1  36    // padded row stride (words): %4==0 (float4 align), %32==4 (conflict-free)

__global__ void __launch_bounds__(128) zkern(const float* __restrict__ h) {
    __shared__ float sh_h[TS1 * P1];    // ~36.9 KB
    __shared__ float sh_A[RR * TK1];    // 2 KB  [r][k]

    const int b   = blockIdx.z;
    const int ksp = blockIdx.y;
    const int s0  = blockIdx.x * TS1;
    const int tid = threadIdx.x;
    const int w   = tid >> 5;
    const int l   = tid & 31;

    unsigned long long accA[RR], accB[RR];
#pragma unroll
    for (int r = 0; r < RR; r++) { accA[r] = 0ULL; accB[r] = 0ULL; }

    const float* hb = h + ((size_t)b * SS + s0) * DIN;
    const int kbase0 = ksp * 512;

    const int sl1 = w * 64 + l;     // local s for compute
    const int sl2 = sl1 + 32;

    for (int c = 0; c < 16; c++) {
        const int kb = kbase0 + c * TK1;
        // --- stage h tile [256 s][32 k], coalesced LDG.128, conflict-free STS.128 ---
#pragma unroll
        for (int it = 0; it < 16; it++) {
            int idx = (it * 128 + tid) * 4;   // 0..8191
            int row = idx >> 5;
            int col = idx & 31;
            float4 v = *(const float4*)(hb + (size_t)row * DIN + kb + col);
            *(float4*)&sh_h[row * P1 + col] = v;
        }
        // --- stage A chunk [16 r][32 k] ---
        {
            int idx = tid * 4;                // 0..511
            int r   = idx >> 5;
            int col = idx & 31;
            float4 v = *(const float4*)&g_Amix[((size_t)(b * RR + r)) * DIN + kb + col];
            *(float4*)&sh_A[r * TK1 + col] = v;
        }
        __syncthreads();

#pragma unroll
        for (int k0 = 0; k0 < TK1; k0 += 4) {
            ulonglong2 ha = *(const ulonglong2*)&sh_h[sl1 * P1 + k0];
            ulonglong2 hc = *(const ulonglong2*)&sh_h[sl2 * P1 + k0];
#pragma unroll
            for (int r = 0; r < RR; r++) {
                ulonglong2 a = *(const ulonglong2*)&sh_A[r * TK1 + k0];  // warp-broadcast
                fma2(accA[r], ha.x, a.x);
                fma2(accA[r], ha.y, a.y);
                fma2(accB[r], hc.x, a.x);
                fma2(accB[r], hc.y, a.y);
            }
        }
        __syncthreads();
    }

    // epilogue: combine packed lanes, write 16 floats per s (4x STG.128)
    {
        int sg1 = s0 + sl1;
        int sg2 = s0 + sl2;
        float v1[RR], v2[RR];
#pragma unroll
        for (int r = 0; r < RR; r++) {
            float2 p = unpack2(accA[r]); v1[r] = p.x + p.y;
            float2 q = unpack2(accB[r]); v2[r] = q.x + q.y;
        }
        float* d1 = &g_zpart[ksp][((size_t)(b * SS + sg1)) * RR];
        float* d2 = &g_zpart[ksp][((size_t)(b * SS + sg2)) * RR];
#pragma unroll
        for (int q = 0; q < 4; q++) {
            *(float4*)&d1[4 * q] = make_float4(v1[4*q], v1[4*q+1], v1[4*q+2], v1[4*q+3]);
            *(float4*)&d2[4 * q] = make_float4(v2[4*q], v2[4*q+1], v2[4*q+2], v2[4*q+3]);
        }
    }
}

// ---------------- dkern: delta[b,s,o] = sum_r BT[b,r,o] * z[b,s,r] ----------------
// grid: (oTiles=8, sTiles=32, b=8), block = 256. Tile: 64 s x 256 o.
#define OT  256
#define ZP  66    // padded z stride

__global__ void __launch_bounds__(256) dkern(float* __restrict__ out) {
    __shared__ float shB[RR * OT];   // 16 KB, [r][o]
    __shared__ float shZ[RR * ZP];   // ~4.1 KB, [r][s] padded

    const int b   = blockIdx.z;
    const int s0  = blockIdx.y * 64;
    const int o0  = blockIdx.x * OT;
    const int tid = threadIdx.x;
    const int w   = tid >> 5;
    const int l   = tid & 31;

    // stage BT tile: 4096 floats
#pragma unroll
    for (int it = 0; it < 4; it++) {
        int idx = (it * 256 + tid) * 4;   // 0..4095
        int r   = idx >> 8;
        int o   = idx & 255;
        *(float4*)&shB[r * OT + o] =
            *(const float4*)&g_BT[((size_t)(b * RR + r)) * DOUT + o0 + o];
    }
    // stage z tile (sum 4 k-splits): 64 s x 16 r
    for (int idx = tid; idx < 64 * RR; idx += 256) {
        int s = idx >> 4;
        int r = idx & 15;
        size_t gi = ((size_t)(b * SS + s0 + s)) * RR + r;
        float v = g_zpart[0][gi] + g_zpart[1][gi] + g_zpart[2][gi] + g_zpart[3][gi];
        shZ[r * ZP + s] = v;
    }
    __syncthreads();

    // thread computes 8 s (warp-uniform) x 8 o (4 packed pairs)
    unsigned long long acc[8][4];
#pragma unroll
    for (int j = 0; j < 8; j++)
#pragma unroll
        for (int j2 = 0; j2 < 4; j2++) acc[j][j2] = 0ULL;

#pragma unroll
    for (int r = 0; r < RR; r++) {
        unsigned long long bo[4];
#pragma unroll
        for (int j2 = 0; j2 < 4; j2++)
            bo[j2] = *(const unsigned long long*)&shB[r * OT + 2 * l + 64 * j2];
#pragma unroll
        for (int j = 0; j < 8; j++) {
            float zv = shZ[r * ZP + 8 * w + j];   // warp-broadcast
            unsigned long long zz = pack2(zv, zv);
#pragma unroll
            for (int j2 = 0; j2 < 4; j2++) fma2(acc[j][j2], zz, bo[j2]);
        }
    }

    // coalesced STG.64 stores
#pragma unroll
    for (int j = 0; j < 8; j++) {
        size_t base = ((size_t)b * SS + (s0 + 8 * w + j)) * (size_t)DOUT + o0 + 2 * l;
#pragma unroll
        for (int j2 = 0; j2 < 4; j2++)
            *(unsigned long long*)&out[base + 64 * j2] = acc[j][j2];
    }
}

// ---------------- launch ----------------
extern "C" void kernel_launch(void* const* d_in, const int* in_sizes, int n_in,
                              void* d_out, int out_size) {
    const float* h     = (const float*)d_in[0];   // [8, 2048, 2048]
    const float* alpha = (const float*)d_in[1];   // [8, 16]
    const float* Abank = (const float*)d_in[2];   // [16, 16, 2048]
    const float* Bbank = (const float*)d_in[3];   // [16, 2048, 16]
    float* out = (float*)d_out;                   // [8, 2048, 2048]

    mixA_kernel<<<dim3(RR, BB), 256>>>(alpha, Abank);
    mixB_kernel<<<dim3(DOUT / 256, BB), 256>>>(alpha, Bbank);
    zkern<<<dim3(SS / TS1, 4, BB), 128>>>(h);
    dkern<<<dim3(DOUT / OT, SS / 64, BB), 256>>>(out);
}

// round 6
// speedup vs baseline: 1.2685x; 1.2685x over previous
#include <cuda_runtime.h>
#include <cuda_bf16.h>
#include <cstdint>

// Problem constants (fixed by reference setup_inputs)
#define BB   8
#define SS   2048
#define KK   16
#define RR   16
#define DIN  2048
#define DOUT 2048
#define KSP  8      // k-splits for zkern

typedef unsigned long long ull;

// Scratch (device globals: allocation-rule safe)
__device__ float g_Amix[BB * RR * DIN];            // [b][r][i]        1 MB
__device__ float g_BT[BB * RR * DOUT];             // [b][r][o]        1 MB
__device__ float g_z2[BB * SS * KSP * RR];         // [b][s][ksp][r]   8 MB

// ---------------- f32x2 packed-FMA helpers (sm_100+) ----------------
__device__ __forceinline__ ull pack2(float x, float y) {
    ull r; asm("mov.b64 %0, {%1,%2};" : "=l"(r) : "f"(x), "f"(y)); return r;
}
__device__ __forceinline__ float2 unpack2(ull v) {
    float2 f; asm("mov.b64 {%0,%1}, %2;" : "=f"(f.x), "=f"(f.y) : "l"(v)); return f;
}
__device__ __forceinline__ void fma2(ull& c, ull a, ull b) {
    asm("fma.rn.f32x2 %0, %1, %2, %3;" : "=l"(c) : "l"(a), "l"(b), "l"(c));
}

// ---------------- fused mixer: A_mixed and BT in one launch ----------------
// blocks 0..127   : A-mix  (b = blk>>4, r = blk&15), row of DIN
// blocks 128..191 : B-mix  (q = blk-128, b = q>>3, o-tile = q&7)
__global__ void __launch_bounds__(256) mix_kernel(const float* __restrict__ alpha,
                                                  const float* __restrict__ Abank,
                                                  const float* __restrict__ Bbank) {
    const int blk = blockIdx.x;
    const int tid = threadIdx.x;
    __shared__ float al[KK];

    if (blk < 128) {
        const int b = blk >> 4, r = blk & 15;
        if (tid < KK) al[tid] = alpha[b * KK + tid];
        __syncthreads();
        for (int i = tid * 4; i < DIN; i += 256 * 4) {
            float4 acc = make_float4(0.f, 0.f, 0.f, 0.f);
#pragma unroll
            for (int k = 0; k < KK; k++) {
                float a = al[k];
                float4 v = *(const float4*)&Abank[((size_t)(k * RR + r)) * DIN + i];
                acc.x = fmaf(a, v.x, acc.x);
                acc.y = fmaf(a, v.y, acc.y);
                acc.z = fmaf(a, v.z, acc.z);
                acc.w = fmaf(a, v.w, acc.w);
            }
            *(float4*)&g_Amix[((size_t)(b * RR + r)) * DIN + i] = acc;
        }
    } else {
        const int q = blk - 128;
        const int b = q >> 3;
        const int o = (q & 7) * 256 + tid;
        if (tid < KK) al[tid] = alpha[b * KK + tid];
        __syncthreads();

        float acc[RR];
#pragma unroll
        for (int r = 0; r < RR; r++) acc[r] = 0.f;
#pragma unroll
        for (int k = 0; k < KK; k++) {
            float a = al[k];
            const float4* p = (const float4*)&Bbank[(((size_t)k * DOUT) + o) * RR];
#pragma unroll
            for (int qq = 0; qq < 4; qq++) {
                float4 v = p[qq];
                acc[4 * qq + 0] = fmaf(a, v.x, acc[4 * qq + 0]);
                acc[4 * qq + 1] = fmaf(a, v.y, acc[4 * qq + 1]);
                acc[4 * qq + 2] = fmaf(a, v.z, acc[4 * qq + 2]);
                acc[4 * qq + 3] = fmaf(a, v.w, acc[4 * qq + 3]);
            }
        }
#pragma unroll
        for (int r = 0; r < RR; r++)
            g_BT[((size_t)(b * RR + r)) * DOUT + o] = acc[r];
    }
}

// ---------------- zkern: z[b,s,ksp,r] = sum_{i in split} A_mixed[b,r,i]*h[b,s,i] --------
// grid (sTiles=8, KSP=8, b=8) = 512 blocks, 256 threads (8 warps).
// Warp-group split over r: warps 0-3 -> r 0..7, warps 4-7 -> r 8..15; both
// groups share the staged h tile so h is read from HBM exactly once.
#define TS1 256   // s rows per block
#define TK1 32    // k chunk
#define P1  36    // padded row stride: %4==0 (f4 align), %32==4 (phase-conflict-free)

__global__ void __launch_bounds__(256) zkern(const float* __restrict__ h) {
    __shared__ float sh_h[TS1 * P1];    // 36.9 KB
    __shared__ float sh_A[RR * TK1];    // 2 KB  [r][k]

    const int b   = blockIdx.z;
    const int ksp = blockIdx.y;
    const int s0  = blockIdx.x * TS1;
    const int tid = threadIdx.x;
    const int w   = tid >> 5;
    const int l   = tid & 31;
    const int g   = w >> 2;           // r-group
    const int wl  = w & 3;            // warp within group
    const int rbase = g * 8;
    const int sl1 = wl * 64 + l;      // two rows per thread
    const int sl2 = sl1 + 32;

    ull accA[8], accB[8];
#pragma unroll
    for (int r = 0; r < 8; r++) { accA[r] = 0ULL; accB[r] = 0ULL; }

    const float* hb = h + ((size_t)b * SS + s0) * DIN;
    const int kbase0 = ksp * (DIN / KSP);   // 256-wide split

    for (int c = 0; c < (DIN / KSP) / TK1; c++) {   // 8 chunks
        const int kb = kbase0 + c * TK1;
        // stage h tile [256 s][32 k]: 2048 float4 / 256 thr = 8 each, coalesced
#pragma unroll
        for (int it = 0; it < 8; it++) {
            int idx = (it * 256 + tid) * 4;      // 0..8191
            int row = idx >> 5;
            int col = idx & 31;
            *(float4*)&sh_h[row * P1 + col] =
                *(const float4*)(hb + (size_t)row * DIN + kb + col);
        }
        // stage A chunk [16 r][32 k]: 128 float4, threads 0..127
        if (tid < 128) {
            int idx = tid * 4;
            int r   = idx >> 5;
            int col = idx & 31;
            *(float4*)&sh_A[r * TK1 + col] =
                *(const float4*)&g_Amix[((size_t)(b * RR + r)) * DIN + kb + col];
        }
        __syncthreads();

#pragma unroll
        for (int k0 = 0; k0 < TK1; k0 += 4) {
            ulonglong2 ha = *(const ulonglong2*)&sh_h[sl1 * P1 + k0];
            ulonglong2 hc = *(const ulonglong2*)&sh_h[sl2 * P1 + k0];
#pragma unroll
            for (int r = 0; r < 8; r++) {
                ulonglong2 a = *(const ulonglong2*)&sh_A[(rbase + r) * TK1 + k0]; // broadcast
                fma2(accA[r], ha.x, a.x);
                fma2(accA[r], ha.y, a.y);
                fma2(accB[r], hc.x, a.x);
                fma2(accB[r], hc.y, a.y);
            }
        }
        __syncthreads();
    }

    // epilogue: fold packed halves, write 8 floats per (row, group): 2x STG.128
    float v1[8], v2[8];
#pragma unroll
    for (int r = 0; r < 8; r++) {
        float2 p = unpack2(accA[r]); v1[r] = p.x + p.y;
        float2 q = unpack2(accB[r]); v2[r] = q.x + q.y;
    }
    size_t base1 = ((size_t)(b * SS + s0 + sl1) * KSP + ksp) * RR + rbase;
    size_t base2 = ((size_t)(b * SS + s0 + sl2) * KSP + ksp) * RR + rbase;
    *(float4*)&g_z2[base1]     = make_float4(v1[0], v1[1], v1[2], v1[3]);
    *(float4*)&g_z2[base1 + 4] = make_float4(v1[4], v1[5], v1[6], v1[7]);
    *(float4*)&g_z2[base2]     = make_float4(v2[0], v2[1], v2[2], v2[3]);
    *(float4*)&g_z2[base2 + 4] = make_float4(v2[4], v2[5], v2[6], v2[7]);
}

// ---------------- dkern: delta[b,s,o] = sum_r BT[b,r,o] * z[b,s,r] ----------------
// grid (oTiles=8, sTiles=64, b=8) = 4096 blocks, 256 threads.
// Tile 32 s x 256 o; thread = 4 s (warp-uniform) x 8 o (two float4 groups).
#define OT  256
#define ST2 32
#define ZP  33

__global__ void __launch_bounds__(256) dkern(float* __restrict__ out) {
    __shared__ float shB[RR * OT];   // 16 KB  [r][o]
    __shared__ float shZ[RR * ZP];   // 2.1 KB [r][s] padded

    const int b   = blockIdx.z;
    const int s0  = blockIdx.y * ST2;
    const int o0  = blockIdx.x * OT;
    const int tid = threadIdx.x;
    const int w   = tid >> 5;
    const int l   = tid & 31;

    // stage BT tile: 4096 floats = 1024 float4 / 256 thr = 4 each
#pragma unroll
    for (int it = 0; it < 4; it++) {
        int idx = (it * 256 + tid) * 4;   // 0..4095
        int r   = idx >> 8;
        int o   = idx & 255;
        *(float4*)&shB[r * OT + o] =
            *(const float4*)&g_BT[((size_t)(b * RR + r)) * DOUT + o0 + o];
    }
    // stage z tile: sum KSP partials per (s, r); coalesced over r
#pragma unroll
    for (int p = tid; p < ST2 * RR; p += 256) {
        int s = p >> 4;
        int r = p & 15;
        const float* zp = &g_z2[((size_t)(b * SS + s0 + s) * KSP) * RR + r];
        float v = 0.f;
#pragma unroll
        for (int j = 0; j < KSP; j++) v += zp[j * RR];
        shZ[r * ZP + s] = v;
    }
    __syncthreads();

    // acc[s][h][pair]: o = 4*l + 128*h + {0,1 | 2,3}
    ull acc[4][2][2];
#pragma unroll
    for (int j = 0; j < 4; j++)
#pragma unroll
        for (int hh = 0; hh < 2; hh++) { acc[j][hh][0] = 0ULL; acc[j][hh][1] = 0ULL; }

    const int sb = 4 * w;
#pragma unroll
    for (int r = 0; r < RR; r++) {
        ulonglong2 bo[2];
#pragma unroll
        for (int hh = 0; hh < 2; hh++)
            bo[hh] = *(const ulonglong2*)&shB[r * OT + 4 * l + 128 * hh];
#pragma unroll
        for (int j = 0; j < 4; j++) {
            float zv = shZ[r * ZP + sb + j];   // warp-broadcast
            ull zz = pack2(zv, zv);
#pragma unroll
            for (int hh = 0; hh < 2; hh++) {
                fma2(acc[j][hh][0], zz, bo[hh].x);
                fma2(acc[j][hh][1], zz, bo[hh].y);
            }
        }
    }

    // 8x STG.128, fully coalesced
#pragma unroll
    for (int j = 0; j < 4; j++) {
        size_t base = ((size_t)b * SS + (s0 + sb + j)) * (size_t)DOUT + o0;
#pragma unroll
        for (int hh = 0; hh < 2; hh++) {
            ulonglong2 v;
            v.x = acc[j][hh][0];
            v.y = acc[j][hh][1];
            *(ulonglong2*)&out[base + 4 * l + 128 * hh] = v;
        }
    }
}

// ---------------- launch ----------------
extern "C" void kernel_launch(void* const* d_in, const int* in_sizes, int n_in,
                              void* d_out, int out_size) {
    const float* h     = (const float*)d_in[0];   // [8, 2048, 2048]
    const float* alpha = (const float*)d_in[1];   // [8, 16]
    const float* Abank = (const float*)d_in[2];   // [16, 16, 2048]
    const float* Bbank = (const float*)d_in[3];   // [16, 2048, 16]
    float* out = (float*)d_out;                   // [8, 2048, 2048]

    // Prefer max shared-memory carveout so smem never caps occupancy below regs.
    cudaFuncSetAttribute(zkern, cudaFuncAttributePreferredSharedMemoryCarveout, 100);
    cudaFuncSetAttribute(dkern, cudaFuncAttributePreferredSharedMemoryCarveout, 100);

    mix_kernel<<<192, 256>>>(alpha, Abank, Bbank);
    zkern<<<dim3(SS / TS1, KSP, BB), 256>>>(h);
    dkern<<<dim3(DOUT / OT, SS / ST2, BB), 256>>>(out);
}

// round 8
// speedup vs baseline: 1.3346x; 1.0521x over previous
#include <cuda_runtime.h>
#include <cuda_bf16.h>
#include <cstdint>

// Problem constants (fixed by reference setup_inputs)
#define BB   8
#define SS   2048
#define KK   16
#define RR   16
#define DIN  2048
#define DOUT 2048
#define KSP  8      // k-splits for zkern

typedef unsigned long long ull;

// Scratch (device globals: allocation-rule safe)
__device__ float g_Amix[BB * RR * DIN];            // [b][r][i]        1 MB
__device__ float g_BT[BB * RR * DOUT];             // [b][r][o]        1 MB
__device__ float g_z2[BB * SS * KSP * RR];         // [b][s][ksp][r]   8 MB

// ---------------- f32x2 packed-FMA helpers (sm_100+) ----------------
__device__ __forceinline__ ull pack2(float x, float y) {
    ull r; asm("mov.b64 %0, {%1,%2};" : "=l"(r) : "f"(x), "f"(y)); return r;
}
__device__ __forceinline__ float2 unpack2(ull v) {
    float2 f; asm("mov.b64 {%0,%1}, %2;" : "=f"(f.x), "=f"(f.y) : "l"(v)); return f;
}
__device__ __forceinline__ void fma2(ull& c, ull a, ull b) {
    asm("fma.rn.f32x2 %0, %1, %2, %3;" : "=l"(c) : "l"(a), "l"(b), "l"(c));
}

// ---------------- cp.async helpers ----------------
__device__ __forceinline__ uint32_t smem_u32(const void* p) {
    return (uint32_t)__cvta_generic_to_shared(p);
}
__device__ __forceinline__ void cp16(uint32_t saddr, const void* g) {
    asm volatile("cp.async.ca.shared.global [%0], [%1], 16;" :: "r"(saddr), "l"(g));
}
__device__ __forceinline__ void cp_commit() {
    asm volatile("cp.async.commit_group;");
}
template <int N>
__device__ __forceinline__ void cp_wait() {
    asm volatile("cp.async.wait_group %0;" :: "n"(N));
}

// ---------------- fused mixer ----------------
// blocks [0, 256)   : A-mix. aid = blk: half = aid&1, r = (aid>>1)&15, b = aid>>5.
//                     256 thr x 1 float4 over a 1024-wide DIN half; 16 LDG in flight.
// blocks [256, 320) : B-mix. q = blk-256: b = q>>3, o-tile = q&7 (256 o's).
__global__ void __launch_bounds__(256) mix_kernel(const float* __restrict__ alpha,
                                                  const float* __restrict__ Abank,
                                                  const float* __restrict__ Bbank) {
    const int blk = blockIdx.x;
    const int tid = threadIdx.x;
    __shared__ float al[KK];

    if (blk < 256) {
        const int half = blk & 1;
        const int r    = (blk >> 1) & 15;
        const int b    = blk >> 5;
        if (tid < KK) al[tid] = alpha[b * KK + tid];
        __syncthreads();
        const int i = half * 1024 + tid * 4;
        float4 acc = make_float4(0.f, 0.f, 0.f, 0.f);
#pragma unroll
        for (int k = 0; k < KK; k++) {
            float a = al[k];
            float4 v = *(const float4*)&Abank[((size_t)(k * RR + r)) * DIN + i];
            acc.x = fmaf(a, v.x, acc.x);
            acc.y = fmaf(a, v.y, acc.y);
            acc.z = fmaf(a, v.z, acc.z);
            acc.w = fmaf(a, v.w, acc.w);
        }
        *(float4*)&g_Amix[((size_t)(b * RR + r)) * DIN + i] = acc;
    } else {
        const int q = blk - 256;
        const int b = q >> 3;
        const int o = (q & 7) * 256 + tid;
        if (tid < KK) al[tid] = alpha[b * KK + tid];
        __syncthreads();

        float acc[RR];
#pragma unroll
        for (int r = 0; r < RR; r++) acc[r] = 0.f;
#pragma unroll
        for (int k = 0; k < KK; k++) {
            float a = al[k];
            const float4* p = (const float4*)&Bbank[(((size_t)k * DOUT) + o) * RR];
#pragma unroll
            for (int qq = 0; qq < 4; qq++) {
                float4 v = p[qq];
                acc[4 * qq + 0] = fmaf(a, v.x, acc[4 * qq + 0]);
                acc[4 * qq + 1] = fmaf(a, v.y, acc[4 * qq + 1]);
                acc[4 * qq + 2] = fmaf(a, v.z, acc[4 * qq + 2]);
                acc[4 * qq + 3] = fmaf(a, v.w, acc[4 * qq + 3]);
            }
        }
#pragma unroll
        for (int r = 0; r < RR; r++)
            g_BT[((size_t)(b * RR + r)) * DOUT + o] = acc[r];
    }
}

// ---------------- zkern: z[b,s,ksp,r] = sum_{i in split} A_mixed[b,r,i]*h[b,s,i] --------
// grid (sTiles=16, KSP=8, b=8) = 1024 blocks, 256 threads (8 warps).
// Warp-group split over r: warps 0-3 -> r 0..7, warps 4-7 -> r 8..15; the h tile is
// staged once and shared. Double-buffered cp.async pipeline hides DRAM latency.
#define TS1 128   // s rows per block (1 per thread per group)
#define TK1 32    // k chunk
#define P1  36    // padded row stride: %4==0 (f4 align), %32==4 (phase-conflict-free)
#define NCH ((DIN / KSP) / TK1)   // 8 chunks

__global__ void __launch_bounds__(256, 4) zkern(const float* __restrict__ h) {
    __shared__ float sh_h[2][TS1 * P1];   // 2 x 18.4 KB
    __shared__ float sh_A[2][RR * TK1];   // 2 x 2 KB

    const int b   = blockIdx.z;
    const int ksp = blockIdx.y;
    const int s0  = blockIdx.x * TS1;
    const int tid = threadIdx.x;
    const int w   = tid >> 5;
    const int l   = tid & 31;
    const int g   = w >> 2;            // r-group (0/1)
    const int wl  = w & 3;             // warp within group
    const int rbase = g * 8;
    const int sl  = wl * 32 + l;       // this thread's s row

    ull acc[8];
#pragma unroll
    for (int r = 0; r < 8; r++) acc[r] = 0ULL;

    const float* hb = h + ((size_t)b * SS + s0) * DIN;
    const int kbase0 = ksp * (DIN / KSP);

    // stage chunk c into buffer buf
    auto stage = [&](int c, int buf) {
        const int kb = kbase0 + c * TK1;
        // h tile [128 s][32 k] = 1024 float4; 4 per thread, coalesced (8 thr/row)
#pragma unroll
        for (int it = 0; it < 4; it++) {
            int idx  = it * 256 + tid;
            int row  = idx >> 3;
            int col4 = idx & 7;
            cp16(smem_u32(&sh_h[buf][row * P1 + col4 * 4]),
                 hb + (size_t)row * DIN + kb + col4 * 4);
        }
        // A chunk [16 r][32 k] = 128 float4; threads 0..127
        if (tid < 128) {
            int r    = tid >> 3;
            int col4 = tid & 7;
            cp16(smem_u32(&sh_A[buf][r * TK1 + col4 * 4]),
                 &g_Amix[((size_t)(b * RR + r)) * DIN + kb + col4 * 4]);
        }
        cp_commit();
    };

    stage(0, 0);
    for (int c = 0; c < NCH; c++) {
        const int buf = c & 1;
        if (c + 1 < NCH) {
            stage(c + 1, buf ^ 1);
            cp_wait<1>();          // chunk c complete, c+1 in flight
        } else {
            cp_wait<0>();
        }
        __syncthreads();

#pragma unroll
        for (int k0 = 0; k0 < TK1; k0 += 4) {
            ulonglong2 ha = *(const ulonglong2*)&sh_h[buf][sl * P1 + k0];
#pragma unroll
            for (int r = 0; r < 8; r++) {
                ulonglong2 a = *(const ulonglong2*)&sh_A[buf][(rbase + r) * TK1 + k0];
                fma2(acc[r], ha.x, a.x);
                fma2(acc[r], ha.y, a.y);
            }
        }
        __syncthreads();   // done reading buf before it is re-staged
    }

    // epilogue: fold packed halves, 2x STG.128 per thread
    float v[8];
#pragma unroll
    for (int r = 0; r < 8; r++) {
        float2 p = unpack2(acc[r]);
        v[r] = p.x + p.y;
    }
    size_t base = ((size_t)(b * SS + s0 + sl) * KSP + ksp) * RR + rbase;
    *(float4*)&g_z2[base]     = make_float4(v[0], v[1], v[2], v[3]);
    *(float4*)&g_z2[base + 4] = make_float4(v[4], v[5], v[6], v[7]);
}

// ---------------- dkern: delta[b,s,o] = sum_r BT[b,r,o] * z[b,s,r] ----------------
// grid (oTiles=8, sTiles=64, b=8) = 4096 blocks, 256 threads.
// Tile 32 s x 256 o; thread = 4 s (warp-uniform) x 8 o (two float4 groups).
#define OT  256
#define ST2 32
#define ZP  33

__global__ void __launch_bounds__(256, 3) dkern(float* __restrict__ out) {
    __shared__ float shB[RR * OT];   // 16 KB  [r][o]
    __shared__ float shZ[RR * ZP];   // 2.1 KB [r][s] padded

    const int b   = blockIdx.z;
    const int s0  = blockIdx.y * ST2;
    const int o0  = blockIdx.x * OT;
    const int tid = threadIdx.x;
    const int w   = tid >> 5;
    const int l   = tid & 31;

    // stage BT tile: 1024 float4 / 256 thr = 4 each
#pragma unroll
    for (int it = 0; it < 4; it++) {
        int idx = (it * 256 + tid) * 4;
        int r   = idx >> 8;
        int o   = idx & 255;
        *(float4*)&shB[r * OT + o] =
            *(const float4*)&g_BT[((size_t)(b * RR + r)) * DOUT + o0 + o];
    }
    // stage z tile: sum KSP partials per (s, r)
#pragma unroll
    for (int p = tid; p < ST2 * RR; p += 256) {
        int s = p >> 4;
        int r = p & 15;
        const float* zp = &g_z2[((size_t)(b * SS + s0 + s) * KSP) * RR + r];
        float v = 0.f;
#pragma unroll
        for (int j = 0; j < KSP; j++) v += zp[j * RR];
        shZ[r * ZP + s] = v;
    }
    __syncthreads();

    // acc[s][h][pair]: o = 4*l + 128*h + {0,1 | 2,3}
    ull acc[4][2][2];
#pragma unroll
    for (int j = 0; j < 4; j++)
#pragma unroll
        for (int hh = 0; hh < 2; hh++) { acc[j][hh][0] = 0ULL; acc[j][hh][1] = 0ULL; }

    const int sb = 4 * w;
#pragma unroll
    for (int r = 0; r < RR; r++) {
        ulonglong2 bo[2];
#pragma unroll
        for (int hh = 0; hh < 2; hh++)
            bo[hh] = *(const ulonglong2*)&shB[r * OT + 4 * l + 128 * hh];
#pragma unroll
        for (int j = 0; j < 4; j++) {
            float zv = shZ[r * ZP + sb + j];   // warp-broadcast
            ull zz = pack2(zv, zv);
#pragma unroll
            for (int hh = 0; hh < 2; hh++) {
                fma2(acc[j][hh][0], zz, bo[hh].x);
                fma2(acc[j][hh][1], zz, bo[hh].y);
            }
        }
    }

    // 8x STG.128, fully coalesced
#pragma unroll
    for (int j = 0; j < 4; j++) {
        size_t base = ((size_t)b * SS + (s0 + sb + j)) * (size_t)DOUT + o0;
#pragma unroll
        for (int hh = 0; hh < 2; hh++) {
            ulonglong2 v;
            v.x = acc[j][hh][0];
            v.y = acc[j][hh][1];
            *(ulonglong2*)&out[base + 4 * l + 128 * hh] = v;
        }
    }
}

// ---------------- launch ----------------
extern "C" void kernel_launch(void* const* d_in, const int* in_sizes, int n_in,
                              void* d_out, int out_size) {
    const float* h     = (const float*)d_in[0];   // [8, 2048, 2048]
    const float* alpha = (const float*)d_in[1];   // [8, 16]
    const float* Abank = (const float*)d_in[2];   // [16, 16, 2048]
    const float* Bbank = (const float*)d_in[3];   // [16, 2048, 16]
    float* out = (float*)d_out;                   // [8, 2048, 2048]

    cudaFuncSetAttribute(zkern, cudaFuncAttributePreferredSharedMemoryCarveout, 100);
    cudaFuncSetAttribute(dkern, cudaFuncAttributePreferredSharedMemoryCarveout, 100);

    mix_kernel<<<320, 256>>>(alpha, Abank, Bbank);
    zkern<<<dim3(SS / TS1, KSP, BB), 256>>>(h);
    dkern<<<dim3(DOUT / OT, SS / ST2, BB), 256>>>(out);
}